// round 10
// baseline (speedup 1.0000x reference)
#include <cuda_runtime.h>
#include <cuda_fp16.h>
#include <mma.h>
#include <math.h>
#include <stdint.h>

using namespace nvcuda;
typedef __half fp16;
constexpr int C_=1024, S_=784, M_=6272, HID_=4096, BC_=512, G_=128;

__device__ __align__(16) fp16 g_xnh[M_*C_], g_xnl[M_*C_];
__device__ __align__(16) float g_qkv[M_*3*C_];
__device__ __align__(16) fp16 g_qh[G_*S_*64], g_ql[G_*S_*64], g_kh[G_*S_*64];
__device__ __align__(16) fp16 g_vTh[G_*64*S_];
__device__ __align__(16) float g_bh[G_*S_*28], g_bw[G_*S_*28];
__device__ __align__(16) fp16 g_aoh[M_*C_], g_aol[M_*C_];
__device__ __align__(16) float g_x1[M_*C_];
__device__ __align__(16) fp16 g_mh[M_*HID_], g_ml[M_*HID_];
__device__ __align__(16) float g_x2[M_*C_];
__device__ __align__(16) fp16 g_x2h[M_*C_], g_x2l[M_*C_];
__device__ __align__(16) float g_c1[M_*BC_];
__device__ __align__(16) fp16 g_c1h[M_*BC_], g_c1l[M_*BC_];
__device__ __align__(16) float g_c2[M_*BC_];
__device__ __align__(16) fp16 g_c2h[M_*BC_], g_c2l[M_*BC_];
__device__ __align__(16) float g_c3[M_*C_];
__device__ __align__(16) fp16 g_wah[3*C_*C_];
__device__ __align__(16) fp16 g_wbh[C_*C_];
__device__ __align__(16) fp16 g_wch[HID_*C_];
__device__ __align__(16) fp16 g_wdh[C_*HID_];
__device__ __align__(16) fp16 g_weh[BC_*C_];
__device__ __align__(16) fp16 g_wfh[BC_*9*BC_];
__device__ __align__(16) fp16 g_wgh[C_*BC_];

__device__ __forceinline__ float gelu_f(float x){ return 0.5f*x*(1.0f+erff(x*0.7071067811865475f)); }
__device__ __forceinline__ void split2(float x, fp16&h, fp16&l){
    h = __float2half_rn(x); l = __float2half_rn(x - __half2float(h));
}

__device__ __forceinline__ void cp16(fp16* sm, const fp16* gm, bool pred){
    uint32_t sa = (uint32_t)__cvta_generic_to_shared(sm);
    int sz = pred ? 16 : 0;
    asm volatile("cp.async.ca.shared.global [%0], [%1], 16, %2;" :: "r"(sa), "l"(gm), "r"(sz));
}
#define CP_COMMIT() asm volatile("cp.async.commit_group;")

__device__ __forceinline__ void stage_tile(const fp16* __restrict__ src, int ld,
        int row0, int rmax, int k0, int K, fp16* sm, int tid, int rows){
    for (int i = tid; i < rows*4; i += 256){
        int r = i>>2, cq = i&3;
        int gr = row0 + r, gk = k0 + (cq<<3);
        bool p = (gr < rmax && gk < K);
        cp16(sm + r*40 + (cq<<3), p ? src + (size_t)gr*ld + gk : src, p);
    }
}
__device__ __forceinline__ void stage_conv(const fp16* __restrict__ src, int row0, int k0,
        fp16* sm, int tid){
    int ky = k0/1536, kxr = k0 - ky*1536, kx = kxr>>9, ci0 = kxr&511;
    for (int i = tid; i < 512; i += 256){
        int r = i>>2, cq = i&3;
        int gr = row0 + r;
        bool p = false; const fp16* g = src;
        if (gr < M_){
            int b = gr/S_, rem = gr - b*S_, h = rem/28, w = rem - h*28;
            int ih = h+ky-1, iw = w+kx-1;
            if ((unsigned)ih<28u && (unsigned)iw<28u){
                p = true; g = src + ((size_t)((b*28+ih)*28+iw))*BC_ + ci0 + (cq<<3);
            }
        }
        cp16(sm + r*40 + (cq<<3), g, p);
    }
}

// fp16x2 wmma GEMM: D = (Ah+Al)@Bh^T, 2-stage cp.async pipeline. B given as [N,K].
template<int BN, int EPI, int GATHER>
__global__ void __launch_bounds__(256) mma_gemm(
    const fp16* __restrict__ Ah, const fp16* __restrict__ Al,
    const fp16* __restrict__ Bh,
    float* __restrict__ o0, fp16* __restrict__ o1, fp16* __restrict__ o2,
    int M, int N, int K, int lda, int ldb, int ldc,
    const float* __restrict__ bias, const float* __restrict__ res, int ldres)
{
    constexpr int BM = 128;
    constexpr int WarpsN = 4, WarpsM = 2;
    constexpr int WM = BM/WarpsM, WN = BN/WarpsN;
    constexpr int MI = WM/16, NI = WN/16;
    constexpr int ATILE = BM*40, BTILE = BN*40;
    constexpr int STAGE = 2*ATILE + BTILE;
    extern __shared__ __align__(128) fp16 pool[];

    const int tid = threadIdx.x, warp = tid>>5, lane = tid&31;
    const int bm = blockIdx.x*BM, bn = blockIdx.y*BN;
    const int wrow = (warp/WarpsN)*WM, wcol = (warp%WarpsN)*WN;

    wmma::fragment<wmma::accumulator,16,16,16,float> acc[MI][NI];
    #pragma unroll
    for (int mi=0; mi<MI; mi++)
        #pragma unroll
        for (int ni=0; ni<NI; ni++) wmma::fill_fragment(acc[mi][ni], 0.f);

    const int KC = (K+31)>>5;
    auto issue = [&](int kc, int s){
        fp16* st = pool + s*STAGE;
        int k0 = kc<<5;
        if (GATHER){ stage_conv(Ah, bm, k0, st, tid); stage_conv(Al, bm, k0, st+ATILE, tid); }
        else { stage_tile(Ah, lda, bm, M, k0, K, st, tid, BM);
               stage_tile(Al, lda, bm, M, k0, K, st+ATILE, tid, BM); }
        stage_tile(Bh, ldb, bn, N, k0, K, st+2*ATILE, tid, BN);
        CP_COMMIT();
    };
    issue(0, 0);
    for (int kc = 0; kc < KC; kc++){
        int buf = kc & 1;
        if (kc+1 < KC){
            issue(kc+1, buf^1);
            asm volatile("cp.async.wait_group 1;");
        } else {
            asm volatile("cp.async.wait_group 0;");
        }
        __syncthreads();
        fp16 *Ash = pool + buf*STAGE, *Asl = Ash + ATILE, *Bsh = Ash + 2*ATILE;
        #pragma unroll
        for (int ks=0; ks<2; ks++){
            wmma::fragment<wmma::matrix_b,16,16,16,fp16,wmma::col_major> bh_f[NI];
            #pragma unroll
            for (int ni=0; ni<NI; ni++)
                wmma::load_matrix_sync(bh_f[ni], Bsh + (wcol+ni*16)*40 + ks*16, 40);
            #pragma unroll
            for (int mi=0; mi<MI; mi++){
                wmma::fragment<wmma::matrix_a,16,16,16,fp16,wmma::row_major> ah_f, al_f;
                wmma::load_matrix_sync(ah_f, Ash + (wrow+mi*16)*40 + ks*16, 40);
                wmma::load_matrix_sync(al_f, Asl + (wrow+mi*16)*40 + ks*16, 40);
                #pragma unroll
                for (int ni=0; ni<NI; ni++){
                    wmma::mma_sync(acc[mi][ni], ah_f, bh_f[ni], acc[mi][ni]);
                    wmma::mma_sync(acc[mi][ni], al_f, bh_f[ni], acc[mi][ni]);
                }
            }
        }
        __syncthreads();
    }

    float* eb = reinterpret_cast<float*>(pool) + warp*320;   // 16x20
    #pragma unroll
    for (int mi=0; mi<MI; mi++){
        #pragma unroll
        for (int ni=0; ni<NI; ni++){
            wmma::store_matrix_sync(eb, acc[mi][ni], 20, wmma::mem_row_major);
            __syncwarp();
            int row0 = bm + wrow + mi*16, col0 = bn + wcol + ni*16;
            #pragma unroll
            for (int j=0; j<8; j++){
                int e = lane + j*32, r = e>>4, c = e&15;
                int gr = row0 + r, gc = col0 + c;
                if (gr < M && gc < N){
                    float v = eb[r*20 + c];
                    if (bias) v += bias[gc];
                    if (EPI == 1){ v = gelu_f(v); fp16 h,l; split2(v,h,l);
                        o1[(size_t)gr*ldc+gc]=h; o2[(size_t)gr*ldc+gc]=l; }
                    else if (EPI == 2){ o0[(size_t)gr*ldc+gc] = v + res[(size_t)gr*ldres+gc]; }
                    else if (EPI == 5){ v += res[(size_t)gr*ldres+gc];
                        o0[(size_t)gr*ldc+gc] = v; fp16 h,l; split2(v,h,l);
                        o1[(size_t)gr*ldc+gc]=h; o2[(size_t)gr*ldc+gc]=l; }
                    else o0[(size_t)gr*ldc+gc] = v;
                }
            }
            __syncwarp();
        }
    }
}

// ---------- fused flash-style attention (two-pass, exact softmax) ----------
constexpr int FSM_BYTES = 220160;
__global__ void __launch_bounds__(256) fattn_k(
    const fp16* __restrict__ qh, const fp16* __restrict__ ql,
    const fp16* __restrict__ kh, const fp16* __restrict__ vT,
    const float* __restrict__ bhp, const float* __restrict__ bwp,
    fp16* __restrict__ oh, fp16* __restrict__ ol)
{
    extern __shared__ __align__(128) char fsm[];
    fp16* Qh = (fp16*)fsm;              // 2 chunks x 5120
    fp16* Ql = Qh + 10240;
    fp16* Kt = Ql + 10240;              // [2 buf][2 chunk][5120]; pass2: Vt aliases buf1
    fp16* Vt = Kt + 10240;              // 4 chunks x 2560
    float* S  = (float*)(Kt + 20480);   // 128 x 132
    float* mrow = S + 128*132;
    float* srow = mrow + 128;
    fp16* Ph = (fp16*)(srow + 128);     // 128 x 136
    fp16* Pl = Ph + 128*136;

    const int tid = threadIdx.x, warp = tid>>5, lane = tid&31;
    const int bm = blockIdx.x*128, g = blockIdx.y;
    qh += (size_t)g*S_*64; ql += (size_t)g*S_*64; kh += (size_t)g*S_*64;
    vT += (size_t)g*64*S_;
    bhp += (size_t)g*S_*28; bwp += (size_t)g*S_*28;

    if (tid < 128){ mrow[tid] = -1e30f; srow[tid] = 0.f; }

    stage_tile(qh, 64, bm, S_, 0,  64, Qh,      tid, 128);
    stage_tile(qh, 64, bm, S_, 32, 64, Qh+5120, tid, 128);
    stage_tile(ql, 64, bm, S_, 0,  64, Ql,      tid, 128);
    stage_tile(ql, 64, bm, S_, 32, 64, Ql+5120, tid, 128);
    stage_tile(kh, 64, 0, S_, 0,  64, Kt,       tid, 128);
    stage_tile(kh, 64, 0, S_, 32, 64, Kt+5120,  tid, 128);
    CP_COMMIT();

    const int wrQ = (warp>>2)*64, wcQ = (warp&3)*32;  // QK: 2x4 warps, WM64 WN32
    const int wrA = (warp>>1)*32, wcA = (warp&1)*32;  // AV: 4x2 warps, WM32 WN32

    wmma::fragment<wmma::accumulator,16,16,16,float> oacc[2][2];
    #pragma unroll
    for (int mi=0; mi<2; mi++)
        #pragma unroll
        for (int ni=0; ni<2; ni++) wmma::fill_fragment(oacc[mi][ni], 0.f);

    auto qk_mma = [&](fp16* Kb){
        wmma::fragment<wmma::accumulator,16,16,16,float> sac[4][2];
        #pragma unroll
        for (int mi=0; mi<4; mi++)
            #pragma unroll
            for (int ni=0; ni<2; ni++) wmma::fill_fragment(sac[mi][ni], 0.f);
        #pragma unroll
        for (int c=0; c<2; c++)
            #pragma unroll
            for (int ks=0; ks<2; ks++){
                wmma::fragment<wmma::matrix_b,16,16,16,fp16,wmma::col_major> bf[2];
                #pragma unroll
                for (int ni=0; ni<2; ni++)
                    wmma::load_matrix_sync(bf[ni], Kb + c*5120 + (wcQ+ni*16)*40 + ks*16, 40);
                #pragma unroll
                for (int mi=0; mi<4; mi++){
                    wmma::fragment<wmma::matrix_a,16,16,16,fp16,wmma::row_major> af, alf;
                    wmma::load_matrix_sync(af,  Qh + c*5120 + (wrQ+mi*16)*40 + ks*16, 40);
                    wmma::load_matrix_sync(alf, Ql + c*5120 + (wrQ+mi*16)*40 + ks*16, 40);
                    #pragma unroll
                    for (int ni=0; ni<2; ni++){
                        wmma::mma_sync(sac[mi][ni], af,  bf[ni], sac[mi][ni]);
                        wmma::mma_sync(sac[mi][ni], alf, bf[ni], sac[mi][ni]);
                    }
                }
            }
        #pragma unroll
        for (int mi=0; mi<4; mi++)
            #pragma unroll
            for (int ni=0; ni<2; ni++)
                wmma::store_matrix_sync(S + (wrQ+mi*16)*132 + wcQ+ni*16, sac[mi][ni], 132,
                                        wmma::mem_row_major);
    };

    // ---- pass 1: exact row stats ----
    for (int kt=0; kt<7; kt++){
        int buf = kt&1;
        if (kt+1 < 7){
            fp16* nb = Kt + (buf^1)*10240;
            stage_tile(kh, 64, (kt+1)*128, S_, 0,  64, nb,      tid, 128);
            stage_tile(kh, 64, (kt+1)*128, S_, 32, 64, nb+5120, tid, 128);
            CP_COMMIT();
            asm volatile("cp.async.wait_group 1;");
        } else asm volatile("cp.async.wait_group 0;");
        __syncthreads();
        qk_mma(Kt + buf*10240);
        __syncthreads();
        {
            int row = tid>>1, half = tid&1;
            int grow = bm + row; bool rv = grow < S_;
            float* Sr = S + row*132 + half*64;
            const float* bhr = bhp + (size_t)(rv ? grow : 0)*28;
            const float* bwr = bwp + (size_t)(rv ? grow : 0)*28;
            float lm = -1e30f;
            #pragma unroll 8
            for (int c=0; c<64; c++){
                int gcol = kt*128 + half*64 + c;
                float v = -1e30f;
                if (rv && gcol < S_) v = Sr[c] + bhr[gcol/28] + bwr[gcol%28];
                Sr[c] = v;
                lm = fmaxf(lm, v);
            }
            lm = fmaxf(lm, __shfl_xor_sync(~0u, lm, 1));
            float mprev = mrow[row];
            float newm = fmaxf(mprev, lm);
            float ps = 0.f;
            #pragma unroll 8
            for (int c=0; c<64; c++) ps += __expf(Sr[c] - newm);
            ps += __shfl_xor_sync(~0u, ps, 1);
            __syncwarp();
            if (half == 0){
                srow[row] = srow[row]*__expf(mprev - newm) + ps;
                mrow[row] = newm;
            }
        }
        __syncthreads();
    }
    if (tid < 128) srow[tid] = (srow[tid] > 0.f) ? 1.f/srow[tid] : 0.f;
    __syncthreads();

    // ---- pass 2: recompute scores, normalize, accumulate P@V ----
    for (int kt=0; kt<7; kt++){
        stage_tile(kh, 64, kt*128, S_, 0,  64, Kt,      tid, 128);
        stage_tile(kh, 64, kt*128, S_, 32, 64, Kt+5120, tid, 128);
        #pragma unroll
        for (int ch=0; ch<4; ch++)
            stage_tile(vT, S_, 0, 64, kt*128 + ch*32, S_, Vt + ch*2560, tid, 64);
        CP_COMMIT();
        asm volatile("cp.async.wait_group 0;");
        __syncthreads();
        qk_mma(Kt);
        __syncthreads();
        {
            int row = tid>>1, half = tid&1;
            int grow = bm + row; bool rv = grow < S_;
            float* Sr = S + row*132 + half*64;
            const float* bhr = bhp + (size_t)(rv ? grow : 0)*28;
            const float* bwr = bwp + (size_t)(rv ? grow : 0)*28;
            float m = mrow[row], inv = srow[row];
            fp16* phr = Ph + row*136 + half*64;
            fp16* plr = Pl + row*136 + half*64;
            #pragma unroll 8
            for (int c=0; c<64; c++){
                int gcol = kt*128 + half*64 + c;
                float p = 0.f;
                if (rv && gcol < S_)
                    p = __expf(Sr[c] + bhr[gcol/28] + bwr[gcol%28] - m) * inv;
                fp16 h,l; split2(p,h,l);
                phr[c]=h; plr[c]=l;
            }
        }
        __syncthreads();
        #pragma unroll
        for (int ch=0; ch<4; ch++)
            #pragma unroll
            for (int ks=0; ks<2; ks++){
                wmma::fragment<wmma::matrix_b,16,16,16,fp16,wmma::col_major> bf[2];
                #pragma unroll
                for (int ni=0; ni<2; ni++)
                    wmma::load_matrix_sync(bf[ni], Vt + ch*2560 + (wcA+ni*16)*40 + ks*16, 40);
                #pragma unroll
                for (int mi=0; mi<2; mi++){
                    wmma::fragment<wmma::matrix_a,16,16,16,fp16,wmma::row_major> pf, plf;
                    wmma::load_matrix_sync(pf,  Ph + (wrA+mi*16)*136 + ch*32 + ks*16, 136);
                    wmma::load_matrix_sync(plf, Pl + (wrA+mi*16)*136 + ch*32 + ks*16, 136);
                    #pragma unroll
                    for (int ni=0; ni<2; ni++){
                        wmma::mma_sync(oacc[mi][ni], pf,  bf[ni], oacc[mi][ni]);
                        wmma::mma_sync(oacc[mi][ni], plf, bf[ni], oacc[mi][ni]);
                    }
                }
            }
        __syncthreads();
    }

    // epilogue: scatter split to [B,S,C]
    float* eb = S + warp*320;
    #pragma unroll
    for (int mi=0; mi<2; mi++)
        #pragma unroll
        for (int ni=0; ni<2; ni++){
            wmma::store_matrix_sync(eb, oacc[mi][ni], 20, wmma::mem_row_major);
            __syncwarp();
            int row0 = bm + wrA + mi*16, col0 = wcA + ni*16;
            #pragma unroll
            for (int j=0; j<8; j++){
                int e = lane + j*32, r = e>>4, c = e&15;
                int gr = row0 + r, gc = col0 + c;
                if (gr < S_){
                    size_t o = ((size_t)(g>>4)*S_ + gr)*1024 + (size_t)(g&15)*64 + gc;
                    fp16 h,l; split2(eb[r*20 + c], h, l);
                    oh[o]=h; ol[o]=l;
                }
            }
            __syncwarp();
        }
}

__global__ void ln_k(const float* __restrict__ x, const float* __restrict__ w,
                     const float* __restrict__ bp, float* __restrict__ of,
                     fp16* __restrict__ oh, fp16* __restrict__ ol,
                     int Cw, float eps, int mode, const float* __restrict__ res)
{
    __shared__ float r1[8], r2[8], st[2];
    const int row = blockIdx.x, tid = threadIdx.x, lane = tid&31, wd = tid>>5;
    const float* xr = x + (size_t)row*Cw;
    float s=0.f, sq=0.f;
    for (int i = tid; i < Cw; i += 256){ float t = xr[i]; s += t; sq += t*t; }
    #pragma unroll
    for (int o=16;o;o>>=1){ s+=__shfl_down_sync(~0u,s,o); sq+=__shfl_down_sync(~0u,sq,o); }
    if (lane==0){ r1[wd]=s; r2[wd]=sq; }
    __syncthreads();
    if (tid==0){ float S=0,Q=0; for(int i=0;i<8;i++){S+=r1[i];Q+=r2[i];}
        float m=S/Cw, v=Q/Cw-m*m; st[0]=m; st[1]=rsqrtf(v+eps); }
    __syncthreads();
    float mean=st[0], rstd=st[1];
    for (int i = tid; i < Cw; i += 256){
        float y = (xr[i]-mean)*rstd*w[i] + bp[i];
        if (mode==2) of[(size_t)row*Cw+i] = y + res[(size_t)row*Cw+i];
        else { if (mode==1) y = gelu_f(y);
            fp16 h,l; split2(y,h,l); oh[(size_t)row*Cw+i]=h; ol[(size_t)row*Cw+i]=l; }
    }
}

__global__ void repack_k(const float* __restrict__ qkv,
    fp16* __restrict__ qh, fp16* __restrict__ ql, fp16* __restrict__ kh,
    fp16* __restrict__ vTh)
{
    __shared__ float sv[32][65];
    const int g = blockIdx.y, s0 = blockIdx.x*32, b = g>>4, n = g&15, t = threadIdx.x;
    for (int e = t; e < 2048; e += 256){
        int sl = e>>6, d = e&63, s = s0+sl;
        if (s < S_){
            size_t base = ((size_t)(b*S_+s))*3072 + n*64 + d;
            float qv = qkv[base]*0.125f;
            sv[sl][d] = qkv[base+2048];
            size_t o = ((size_t)g*S_+s)*64 + d;
            fp16 h,l; split2(qv,h,l); qh[o]=h; ql[o]=l;
            kh[o] = __float2half_rn(qkv[base+1024]);
        }
    }
    __syncthreads();
    for (int e = t; e < 2048; e += 256){
        int d = e>>5, j = e&31, s = s0+j;
        if (s < S_)
            vTh[((size_t)g*64+d)*S_ + s] = __float2half_rn(sv[j][d]);
    }
}

__global__ void relbias_k(const float* __restrict__ qkv, const float* __restrict__ rh,
                          const float* __restrict__ rw, float* __restrict__ bh, float* __restrict__ bw)
{
    const int s = blockIdx.x % S_, g = blockIdx.x / S_, b = g>>4, n = g&15;
    __shared__ float qs[64];
    const int t = threadIdx.x;
    qs[t] = qkv[((size_t)(b*S_+s))*3072 + n*64 + t];
    __syncthreads();
    const int h = s/28, w = s%28;
    if (t < 28){
        const float* r = rh + (size_t)(h-t+27)*64; float a=0.f;
        #pragma unroll
        for (int d=0;d<64;d++) a = fmaf(qs[d], r[d], a);
        bh[((size_t)g*S_+s)*28 + t] = a;
    } else if (t >= 32 && t < 60){
        const int l = t-32;
        const float* r = rw + (size_t)(w-l+27)*64; float a=0.f;
        #pragma unroll
        for (int d=0;d<64;d++) a = fmaf(qs[d], r[d], a);
        bw[((size_t)g*S_+s)*28 + l] = a;
    }
}

__global__ void wsplitT_k(const float* __restrict__ Wm, fp16* __restrict__ Th, int K, int N)
{
    __shared__ float s[32][33];
    const int k0 = blockIdx.x*32, n0 = blockIdx.y*32, tx = threadIdx.x, ty = threadIdx.y;
    #pragma unroll
    for (int y=0;y<32;y+=8) s[ty+y][tx] = Wm[(size_t)(k0+ty+y)*N + n0+tx];
    __syncthreads();
    #pragma unroll
    for (int y=0;y<32;y+=8)
        Th[(size_t)(n0+ty+y)*K + k0+tx] = __float2half_rn(s[tx][ty+y]);
}

constexpr int SM128 = (2*128*40 + 128*40)*2*2;   // 61440 B
#define GSA(p, sym) cudaGetSymbolAddress((void**)&p, sym)
extern "C" void kernel_launch(void* const* d_in, const int* in_sizes, int n_in,
                              void* d_out, int out_size)
{
    const float *x=(const float*)d_in[0], *n1w=(const float*)d_in[1], *n1b=(const float*)d_in[2],
        *qkvw=(const float*)d_in[3], *qkvb=(const float*)d_in[4], *pw=(const float*)d_in[5],
        *pb=(const float*)d_in[6], *relh=(const float*)d_in[7], *relw=(const float*)d_in[8],
        *n2w=(const float*)d_in[9], *n2b=(const float*)d_in[10], *f1w=(const float*)d_in[11],
        *f1b=(const float*)d_in[12], *f2w=(const float*)d_in[13], *f2b=(const float*)d_in[14],
        *c1w=(const float*)d_in[15], *l1w=(const float*)d_in[16], *l1b=(const float*)d_in[17],
        *c2w=(const float*)d_in[18], *l2w=(const float*)d_in[19], *l2b=(const float*)d_in[20],
        *c3w=(const float*)d_in[21], *l3w=(const float*)d_in[22], *l3b=(const float*)d_in[23];
    float* out = (float*)d_out;

    float *qkv,*bh,*bw,*x1,*x2,*c1,*c2,*c3;
    fp16 *xnh,*xnl,*qh,*ql,*kh,*vTh,*aoh,*aol,*mh,*ml,*x2h,*x2l,*c1h,*c1l,*c2h,*c2l;
    fp16 *wah,*wbh,*wch,*wdh,*weh,*wfh,*wgh;
    GSA(qkv,g_qkv); GSA(bh,g_bh); GSA(bw,g_bw); GSA(x1,g_x1); GSA(x2,g_x2);
    GSA(c1,g_c1); GSA(c2,g_c2); GSA(c3,g_c3);
    GSA(xnh,g_xnh); GSA(xnl,g_xnl); GSA(qh,g_qh); GSA(ql,g_ql); GSA(kh,g_kh);
    GSA(vTh,g_vTh); GSA(aoh,g_aoh); GSA(aol,g_aol);
    GSA(mh,g_mh); GSA(ml,g_ml); GSA(x2h,g_x2h); GSA(x2l,g_x2l);
    GSA(c1h,g_c1h); GSA(c1l,g_c1l); GSA(c2h,g_c2h); GSA(c2l,g_c2l);
    GSA(wah,g_wah); GSA(wbh,g_wbh); GSA(wch,g_wch); GSA(wdh,g_wdh);
    GSA(weh,g_weh); GSA(wfh,g_wfh); GSA(wgh,g_wgh);

    cudaFuncSetAttribute(mma_gemm<128,0,0>, cudaFuncAttributeMaxDynamicSharedMemorySize, SM128);
    cudaFuncSetAttribute(mma_gemm<128,1,0>, cudaFuncAttributeMaxDynamicSharedMemorySize, SM128);
    cudaFuncSetAttribute(mma_gemm<128,2,0>, cudaFuncAttributeMaxDynamicSharedMemorySize, SM128);
    cudaFuncSetAttribute(mma_gemm<128,5,0>, cudaFuncAttributeMaxDynamicSharedMemorySize, SM128);
    cudaFuncSetAttribute(mma_gemm<128,0,1>, cudaFuncAttributeMaxDynamicSharedMemorySize, SM128);
    cudaFuncSetAttribute(fattn_k, cudaFuncAttributeMaxDynamicSharedMemorySize, FSM_BYTES);

    dim3 wb(32,8);
    wsplitT_k<<<dim3(32,96), wb>>>(qkvw, wah, C_, 3*C_);
    wsplitT_k<<<dim3(32,32), wb>>>(pw,  wbh, C_, C_);
    wsplitT_k<<<dim3(32,128),wb>>>(f1w, wch, C_, HID_);
    wsplitT_k<<<dim3(128,32),wb>>>(f2w, wdh, HID_, C_);
    wsplitT_k<<<dim3(32,16), wb>>>(c1w, weh, C_, BC_);
    wsplitT_k<<<dim3(144,16),wb>>>(c2w, wfh, 9*BC_, BC_);
    wsplitT_k<<<dim3(16,32), wb>>>(c3w, wgh, BC_, C_);

    ln_k<<<M_,256>>>(x, n1w, n1b, nullptr, xnh, xnl, C_, 1e-5f, 0, nullptr);
    mma_gemm<128,0,0><<<dim3(49,24),256,SM128>>>(xnh,xnl,wah, qkv,nullptr,nullptr,
        M_,3*C_,C_, C_,C_,3*C_, qkvb,nullptr,0);
    repack_k<<<dim3(25,G_),256>>>(qkv,qh,ql,kh,vTh);
    relbias_k<<<G_*S_,64>>>(qkv,relh,relw,bh,bw);
    fattn_k<<<dim3(7,G_),256,FSM_BYTES>>>(qh,ql,kh,vTh,bh,bw,aoh,aol);
    mma_gemm<128,2,0><<<dim3(49,8),256,SM128>>>(aoh,aol,wbh, x1,nullptr,nullptr,
        M_,C_,C_, C_,C_,C_, pb,x,C_);
    ln_k<<<M_,256>>>(x1, n2w, n2b, nullptr, xnh, xnl, C_, 1e-5f, 0, nullptr);
    mma_gemm<128,1,0><<<dim3(49,32),256,SM128>>>(xnh,xnl,wch, nullptr,mh,ml,
        M_,HID_,C_, C_,C_,HID_, f1b,nullptr,0);
    mma_gemm<128,5,0><<<dim3(49,8),256,SM128>>>(mh,ml,wdh, x2,x2h,x2l,
        M_,C_,HID_, HID_,HID_,C_, f2b,x1,C_);
    mma_gemm<128,0,0><<<dim3(49,4),256,SM128>>>(x2h,x2l,weh, c1,nullptr,nullptr,
        M_,BC_,C_, C_,C_,BC_, nullptr,nullptr,0);
    ln_k<<<M_,256>>>(c1, l1w, l1b, nullptr, c1h, c1l, BC_, 1e-6f, 1, nullptr);
    mma_gemm<128,0,1><<<dim3(49,4),256,SM128>>>(c1h,c1l,wfh, c2,nullptr,nullptr,
        M_,BC_,9*BC_, 0,9*BC_,BC_, nullptr,nullptr,0);
    ln_k<<<M_,256>>>(c2, l2w, l2b, nullptr, c2h, c2l, BC_, 1e-6f, 1, nullptr);
    mma_gemm<128,0,0><<<dim3(49,8),256,SM128>>>(c2h,c2l,wgh, c3,nullptr,nullptr,
        M_,C_,BC_, BC_,BC_,C_, nullptr,nullptr,0);
    ln_k<<<M_,256>>>(c3, l3w, l3b, out, nullptr, nullptr, C_, 1e-6f, 2, x2);
}

// round 11
// speedup vs baseline: 1.0942x; 1.0942x over previous
#include <cuda_runtime.h>
#include <cuda_fp16.h>
#include <mma.h>
#include <math.h>
#include <stdint.h>

using namespace nvcuda;
typedef __half fp16;
constexpr int C_=1024, S_=784, M_=6272, HID_=4096, BC_=512, G_=128;

__device__ __align__(16) fp16 g_xnh[M_*C_], g_xnl[M_*C_];
__device__ __align__(16) float g_qkv[M_*3*C_];
__device__ __align__(16) fp16 g_qh[G_*S_*64], g_ql[G_*S_*64], g_kh[G_*S_*64];
__device__ __align__(16) fp16 g_vTh[G_*64*S_];
__device__ __align__(16) float g_bh[G_*S_*28], g_bw[G_*S_*28];
__device__ __align__(16) float g_attn[(size_t)G_*S_*S_];
__device__ __align__(16) float2 g_pstat[(size_t)G_*S_*7];
__device__ __align__(16) fp16 g_aoh[M_*C_], g_aol[M_*C_];
__device__ __align__(16) float g_x1[M_*C_];
__device__ __align__(16) fp16 g_mh[M_*HID_], g_ml[M_*HID_];
__device__ __align__(16) float g_x2[M_*C_];
__device__ __align__(16) fp16 g_x2h[M_*C_], g_x2l[M_*C_];
__device__ __align__(16) float g_c1[M_*BC_];
__device__ __align__(16) fp16 g_c1h[M_*BC_], g_c1l[M_*BC_];
__device__ __align__(16) float g_c2[M_*BC_];
__device__ __align__(16) fp16 g_c2h[M_*BC_], g_c2l[M_*BC_];
__device__ __align__(16) float g_c3[M_*C_];
__device__ __align__(16) fp16 g_wah[3*C_*C_];
__device__ __align__(16) fp16 g_wbh[C_*C_];
__device__ __align__(16) fp16 g_wch[HID_*C_];
__device__ __align__(16) fp16 g_wdh[C_*HID_];
__device__ __align__(16) fp16 g_weh[BC_*C_];
__device__ __align__(16) fp16 g_wfh[BC_*9*BC_];
__device__ __align__(16) fp16 g_wgh[C_*BC_];

__device__ __forceinline__ float gelu_f(float x){ return 0.5f*x*(1.0f+erff(x*0.7071067811865475f)); }
__device__ __forceinline__ void split2(float x, fp16&h, fp16&l){
    h = __float2half_rn(x); l = __float2half_rn(x - __half2float(h));
}

__device__ __forceinline__ void cp16(fp16* sm, const fp16* gm, bool pred){
    uint32_t sa = (uint32_t)__cvta_generic_to_shared(sm);
    int sz = pred ? 16 : 0;
    asm volatile("cp.async.ca.shared.global [%0], [%1], 16, %2;" :: "r"(sa), "l"(gm), "r"(sz));
}
#define CP_COMMIT() asm volatile("cp.async.commit_group;")

__device__ __forceinline__ void stage_tile(const fp16* __restrict__ src, int ld,
        int row0, int rmax, int k0, int K, fp16* sm, int tid, int rows){
    for (int i = tid; i < rows*4; i += 256){
        int r = i>>2, cq = i&3;
        int gr = row0 + r, gk = k0 + (cq<<3);
        bool p = (gr < rmax && gk < K);
        cp16(sm + r*40 + (cq<<3), p ? src + (size_t)gr*ld + gk : src, p);
    }
}
__device__ __forceinline__ void stage_conv(const fp16* __restrict__ src, int row0, int k0,
        fp16* sm, int tid){
    int ky = k0/1536, kxr = k0 - ky*1536, kx = kxr>>9, ci0 = kxr&511;
    for (int i = tid; i < 512; i += 256){
        int r = i>>2, cq = i&3;
        int gr = row0 + r;
        bool p = false; const fp16* g = src;
        if (gr < M_){
            int b = gr/S_, rem = gr - b*S_, h = rem/28, w = rem - h*28;
            int ih = h+ky-1, iw = w+kx-1;
            if ((unsigned)ih<28u && (unsigned)iw<28u){
                p = true; g = src + ((size_t)((b*28+ih)*28+iw))*BC_ + ci0 + (cq<<3);
            }
        }
        cp16(sm + r*40 + (cq<<3), g, p);
    }
}

// fp16x2 wmma GEMM: D = (Ah+Al)@Bh^T, 2-stage cp.async pipeline. B given as [N,K].
// EPI 0: fp32(+bias)  1: gelu->split  2: +bias+res->fp32
// EPI 3: +bh+bw->fp32 AND per-tile row stats -> pstat[g,row,blockIdx.y]
// EPI 5: +bias+res->fp32 AND split
template<int BN, int EPI, int GATHER>
__global__ void __launch_bounds__(256) mma_gemm(
    const fp16* __restrict__ Ah, const fp16* __restrict__ Al,
    const fp16* __restrict__ Bh,
    float* __restrict__ o0, fp16* __restrict__ o1, fp16* __restrict__ o2,
    int M, int N, int K, int lda, int ldb, int ldc,
    long long sA, long long sB, long long sC,
    const float* __restrict__ bias, const float* __restrict__ res, int ldres,
    const float* __restrict__ bhp, const float* __restrict__ bwp,
    float2* __restrict__ pstat)
{
    constexpr int BM = 128;
    constexpr int WarpsN = 4, WarpsM = 2;
    constexpr int WM = BM/WarpsM, WN = BN/WarpsN;
    constexpr int MI = WM/16, NI = WN/16;
    constexpr int ATILE = BM*40, BTILE = BN*40;
    constexpr int STAGE = 2*ATILE + BTILE;
    extern __shared__ __align__(128) fp16 pool[];

    const int tid = threadIdx.x, warp = tid>>5, lane = tid&31;
    const int bm = blockIdx.x*BM, bn = blockIdx.y*BN, g = blockIdx.z;
    Ah += (size_t)g*sA; Al += (size_t)g*sA; Bh += (size_t)g*sB;
    const int wrow = (warp/WarpsN)*WM, wcol = (warp%WarpsN)*WN;

    wmma::fragment<wmma::accumulator,16,16,16,float> acc[MI][NI];
    #pragma unroll
    for (int mi=0; mi<MI; mi++)
        #pragma unroll
        for (int ni=0; ni<NI; ni++) wmma::fill_fragment(acc[mi][ni], 0.f);

    const int KC = (K+31)>>5;
    auto issue = [&](int kc, int s){
        fp16* st = pool + s*STAGE;
        int k0 = kc<<5;
        if (GATHER){ stage_conv(Ah, bm, k0, st, tid); stage_conv(Al, bm, k0, st+ATILE, tid); }
        else { stage_tile(Ah, lda, bm, M, k0, K, st, tid, BM);
               stage_tile(Al, lda, bm, M, k0, K, st+ATILE, tid, BM); }
        stage_tile(Bh, ldb, bn, N, k0, K, st+2*ATILE, tid, BN);
        CP_COMMIT();
    };
    issue(0, 0);
    for (int kc = 0; kc < KC; kc++){
        int buf = kc & 1;
        if (kc+1 < KC){
            issue(kc+1, buf^1);
            asm volatile("cp.async.wait_group 1;");
        } else {
            asm volatile("cp.async.wait_group 0;");
        }
        __syncthreads();
        fp16 *Ash = pool + buf*STAGE, *Asl = Ash + ATILE, *Bsh = Ash + 2*ATILE;
        #pragma unroll
        for (int ks=0; ks<2; ks++){
            wmma::fragment<wmma::matrix_b,16,16,16,fp16,wmma::col_major> bh_f[NI];
            #pragma unroll
            for (int ni=0; ni<NI; ni++)
                wmma::load_matrix_sync(bh_f[ni], Bsh + (wcol+ni*16)*40 + ks*16, 40);
            #pragma unroll
            for (int mi=0; mi<MI; mi++){
                wmma::fragment<wmma::matrix_a,16,16,16,fp16,wmma::row_major> ah_f, al_f;
                wmma::load_matrix_sync(ah_f, Ash + (wrow+mi*16)*40 + ks*16, 40);
                wmma::load_matrix_sync(al_f, Asl + (wrow+mi*16)*40 + ks*16, 40);
                #pragma unroll
                for (int ni=0; ni<NI; ni++){
                    wmma::mma_sync(acc[mi][ni], ah_f, bh_f[ni], acc[mi][ni]);
                    wmma::mma_sync(acc[mi][ni], al_f, bh_f[ni], acc[mi][ni]);
                }
            }
        }
        __syncthreads();
    }

    float* eb = reinterpret_cast<float*>(pool) + warp*320;   // 16x20
    float2* sstat = reinterpret_cast<float2*>(reinterpret_cast<float*>(pool) + 4096);
    #pragma unroll
    for (int mi=0; mi<MI; mi++){
        float rm[8], rs[8];
        if (EPI == 3){
            #pragma unroll
            for (int j=0;j<8;j++){ rm[j] = -1e30f; rs[j] = 0.f; }
        }
        #pragma unroll
        for (int ni=0; ni<NI; ni++){
            wmma::store_matrix_sync(eb, acc[mi][ni], 20, wmma::mem_row_major);
            __syncwarp();
            int row0 = bm + wrow + mi*16, col0 = bn + wcol + ni*16;
            #pragma unroll
            for (int j=0; j<8; j++){
                int e = lane + j*32, r = e>>4, c = e&15;
                int gr = row0 + r, gc = col0 + c;
                bool ok = (gr < M) && (gc < N);
                float v = -1e30f;
                if (ok){
                    v = eb[r*20 + c];
                    if (bias) v += bias[gc];
                    if (EPI == 1){ float y = gelu_f(v); fp16 h,l; split2(y,h,l);
                        o1[(size_t)gr*ldc+gc]=h; o2[(size_t)gr*ldc+gc]=l; }
                    else if (EPI == 2){ o0[(size_t)gr*ldc+gc] = v + res[(size_t)gr*ldres+gc]; }
                    else if (EPI == 3){
                        v += bhp[((size_t)g*S_+gr)*28 + gc/28] + bwp[((size_t)g*S_+gr)*28 + gc%28];
                        o0[(size_t)g*sC + (size_t)gr*ldc + gc] = v; }
                    else if (EPI == 5){ float y = v + res[(size_t)gr*ldres+gc];
                        o0[(size_t)gr*ldc+gc] = y; fp16 h,l; split2(y,h,l);
                        o1[(size_t)gr*ldc+gc]=h; o2[(size_t)gr*ldc+gc]=l; }
                    else o0[(size_t)gr*ldc+gc] = v;
                }
                if (EPI == 3){
                    float mt = v;
                    #pragma unroll
                    for (int o=8;o;o>>=1) mt = fmaxf(mt, __shfl_xor_sync(~0u, mt, o));
                    float et = ok ? __expf(v - mt) : 0.f;
                    #pragma unroll
                    for (int o=8;o;o>>=1) et += __shfl_xor_sync(~0u, et, o);
                    float nm = fmaxf(rm[j], mt);
                    if (nm > -1e29f){
                        rs[j] = rs[j]*__expf(rm[j]-nm) + et*__expf(mt-nm);
                        rm[j] = nm;
                    }
                }
            }
            __syncwarp();
        }
        if (EPI == 3){
            #pragma unroll
            for (int j=0;j<8;j++){
                if ((lane & 15) == 0){
                    int rloc = wrow + mi*16 + (lane>>4) + 2*j;
                    sstat[rloc*4 + (wcol>>5)] = make_float2(rm[j], rs[j]);
                }
            }
        }
    }
    if (EPI == 3){
        __syncthreads();
        if (tid < 128){
            float2 a = sstat[tid*4+0], b = sstat[tid*4+1];
            float2 c = sstat[tid*4+2], d = sstat[tid*4+3];
            float m = fmaxf(fmaxf(a.x,b.x), fmaxf(c.x,d.x));
            float s = 0.f;
            if (m > -1e29f)
                s = a.y*__expf(a.x-m) + b.y*__expf(b.x-m)
                  + c.y*__expf(c.x-m) + d.y*__expf(d.x-m);
            int grow = bm + tid;
            if (grow < M)
                pstat[((size_t)g*S_ + grow)*7 + blockIdx.y] = make_float2(m, s);
        }
    }
}

// fused softmax+AV: O[g] = softmax(attn[g]) @ V[g]^T, scatter split to [B,S,C]
__global__ void __launch_bounds__(256) av_k(
    const float* __restrict__ attn, const float2* __restrict__ pstat,
    const fp16* __restrict__ vT, fp16* __restrict__ oh, fp16* __restrict__ ol)
{
    constexpr int KC = 25;
    __shared__ __align__(16) fp16 Ph[2][128*40], Pl[2][128*40], Vs[2][64*40];
    __shared__ float2 st[128];
    const int tid = threadIdx.x, warp = tid>>5, lane = tid&31;
    const int bm = blockIdx.x*128, g = blockIdx.y;
    attn += (size_t)g*S_*S_;
    vT   += (size_t)g*64*S_;
    if (tid < 128){
        int grow = bm + tid;
        if (grow < S_){
            const float2* pp = pstat + ((size_t)g*S_ + grow)*7;
            float2 v[7]; float m = -1e30f;
            #pragma unroll
            for (int t=0;t<7;t++){ v[t]=pp[t]; m=fmaxf(m,v[t].x); }
            float s = 0.f;
            #pragma unroll
            for (int t=0;t<7;t++) s += v[t].y*__expf(v[t].x-m);
            st[tid] = make_float2(m, 1.f/s);
        } else st[tid] = make_float2(0.f, 0.f);
    }
    const int wrow = (warp>>1)*32, wcol = (warp&1)*32;

    wmma::fragment<wmma::accumulator,16,16,16,float> acc[2][2];
    #pragma unroll
    for (int mi=0; mi<2; mi++)
        #pragma unroll
        for (int ni=0; ni<2; ni++) wmma::fill_fragment(acc[mi][ni], 0.f);

    float4 areg[4];
    auto loadA = [&](int kc){
        int k0 = kc<<5;
        #pragma unroll
        for (int j=0; j<4; j++){
            int s = tid + j*256, r = s>>3, cq = s&7;
            int row = bm + r, col = k0 + cq*4;
            if (row < S_ && col+3 < S_)
                areg[j] = *reinterpret_cast<const float4*>(attn + (size_t)row*S_ + col);
            else if (row < S_){
                float t0 = (col   < S_) ? attn[(size_t)row*S_ + col  ] : -1e30f;
                float t1 = (col+1 < S_) ? attn[(size_t)row*S_ + col+1] : -1e30f;
                float t2 = (col+2 < S_) ? attn[(size_t)row*S_ + col+2] : -1e30f;
                float t3 = (col+3 < S_) ? attn[(size_t)row*S_ + col+3] : -1e30f;
                areg[j] = make_float4(t0,t1,t2,t3);
            } else areg[j] = make_float4(-1e30f,-1e30f,-1e30f,-1e30f);
        }
    };
    loadA(0);
    stage_tile(vT, S_, 0, 64, 0, S_, Vs[0], tid, 64);
    CP_COMMIT();
    __syncthreads();   // st[] ready

    for (int kc = 0; kc < KC; kc++){
        int buf = kc & 1;
        #pragma unroll
        for (int j=0; j<4; j++){
            int s = tid + j*256, r = s>>3, cq = s&7;
            float m = st[r].x, inv = st[r].y;
            bool rv = (bm + r) < S_;
            union { fp16 h[4]; uint2 u; } ph, pl;
            float* av = reinterpret_cast<float*>(&areg[j]);
            #pragma unroll
            for (int u=0; u<4; u++){
                float p = rv ? __expf(av[u] - m) * inv : 0.f;
                split2(p, ph.h[u], pl.h[u]);
            }
            *reinterpret_cast<uint2*>(&Ph[buf][r*40 + cq*4]) = ph.u;
            *reinterpret_cast<uint2*>(&Pl[buf][r*40 + cq*4]) = pl.u;
        }
        if (kc+1 < KC){
            loadA(kc+1);
            stage_tile(vT, S_, 0, 64, (kc+1)<<5, S_, Vs[buf^1], tid, 64);
            CP_COMMIT();
            asm volatile("cp.async.wait_group 1;");
        } else {
            asm volatile("cp.async.wait_group 0;");
        }
        __syncthreads();
        #pragma unroll
        for (int ks=0; ks<2; ks++){
            wmma::fragment<wmma::matrix_b,16,16,16,fp16,wmma::col_major> b_f[2];
            #pragma unroll
            for (int ni=0; ni<2; ni++)
                wmma::load_matrix_sync(b_f[ni], Vs[buf] + (wcol+ni*16)*40 + ks*16, 40);
            #pragma unroll
            for (int mi=0; mi<2; mi++){
                wmma::fragment<wmma::matrix_a,16,16,16,fp16,wmma::row_major> ah_f, al_f;
                wmma::load_matrix_sync(ah_f, Ph[buf] + (wrow+mi*16)*40 + ks*16, 40);
                wmma::load_matrix_sync(al_f, Pl[buf] + (wrow+mi*16)*40 + ks*16, 40);
                #pragma unroll
                for (int ni=0; ni<2; ni++){
                    wmma::mma_sync(acc[mi][ni], ah_f, b_f[ni], acc[mi][ni]);
                    wmma::mma_sync(acc[mi][ni], al_f, b_f[ni], acc[mi][ni]);
                }
            }
        }
        __syncthreads();
    }

    float* eb = reinterpret_cast<float*>(Ph) + warp*320;
    #pragma unroll
    for (int mi=0; mi<2; mi++){
        #pragma unroll
        for (int ni=0; ni<2; ni++){
            wmma::store_matrix_sync(eb, acc[mi][ni], 20, wmma::mem_row_major);
            __syncwarp();
            int row0 = bm + wrow + mi*16, col0 = wcol + ni*16;
            #pragma unroll
            for (int j=0; j<8; j++){
                int e = lane + j*32, r = e>>4, c = e&15;
                int gr = row0 + r, gc = col0 + c;
                if (gr < S_){
                    size_t o = ((size_t)(g>>4)*S_ + gr)*1024 + (size_t)(g&15)*64 + gc;
                    fp16 h,l; split2(eb[r*20 + c], h, l);
                    oh[o]=h; ol[o]=l;
                }
            }
            __syncwarp();
        }
    }
}

__global__ void ln_k(const float* __restrict__ x, const float* __restrict__ w,
                     const float* __restrict__ bp, float* __restrict__ of,
                     fp16* __restrict__ oh, fp16* __restrict__ ol,
                     int Cw, float eps, int mode, const float* __restrict__ res)
{
    __shared__ float r1[8], r2[8], st[2];
    const int row = blockIdx.x, tid = threadIdx.x, lane = tid&31, wd = tid>>5;
    const float* xr = x + (size_t)row*Cw;
    float s=0.f, sq=0.f;
    for (int i = tid; i < Cw; i += 256){ float t = xr[i]; s += t; sq += t*t; }
    #pragma unroll
    for (int o=16;o;o>>=1){ s+=__shfl_down_sync(~0u,s,o); sq+=__shfl_down_sync(~0u,sq,o); }
    if (lane==0){ r1[wd]=s; r2[wd]=sq; }
    __syncthreads();
    if (tid==0){ float S=0,Q=0; for(int i=0;i<8;i++){S+=r1[i];Q+=r2[i];}
        float m=S/Cw, v=Q/Cw-m*m; st[0]=m; st[1]=rsqrtf(v+eps); }
    __syncthreads();
    float mean=st[0], rstd=st[1];
    for (int i = tid; i < Cw; i += 256){
        float y = (xr[i]-mean)*rstd*w[i] + bp[i];
        if (mode==2) of[(size_t)row*Cw+i] = y + res[(size_t)row*Cw+i];
        else { if (mode==1) y = gelu_f(y);
            fp16 h,l; split2(y,h,l); oh[(size_t)row*Cw+i]=h; ol[(size_t)row*Cw+i]=l; }
    }
}

__global__ void repack_k(const float* __restrict__ qkv,
    fp16* __restrict__ qh, fp16* __restrict__ ql, fp16* __restrict__ kh,
    fp16* __restrict__ vTh)
{
    __shared__ float sv[32][65];
    const int g = blockIdx.y, s0 = blockIdx.x*32, b = g>>4, n = g&15, t = threadIdx.x;
    for (int e = t; e < 2048; e += 256){
        int sl = e>>6, d = e&63, s = s0+sl;
        if (s < S_){
            size_t base = ((size_t)(b*S_+s))*3072 + n*64 + d;
            float qv = qkv[base]*0.125f;
            sv[sl][d] = qkv[base+2048];
            size_t o = ((size_t)g*S_+s)*64 + d;
            fp16 h,l; split2(qv,h,l); qh[o]=h; ql[o]=l;
            kh[o] = __float2half_rn(qkv[base+1024]);
        }
    }
    __syncthreads();
    for (int e = t; e < 2048; e += 256){
        int d = e>>5, j = e&31, s = s0+j;
        if (s < S_)
            vTh[((size_t)g*64+d)*S_ + s] = __float2half_rn(sv[j][d]);
    }
}

__global__ void relbias_k(const float* __restrict__ qkv, const float* __restrict__ rh,
                          const float* __restrict__ rw, float* __restrict__ bh, float* __restrict__ bw)
{
    const int s = blockIdx.x % S_, g = blockIdx.x / S_, b = g>>4, n = g&15;
    __shared__ float qs[64];
    const int t = threadIdx.x;
    qs[t] = qkv[((size_t)(b*S_+s))*3072 + n*64 + t];
    __syncthreads();
    const int h = s/28, w = s%28;
    if (t < 28){
        const float* r = rh + (size_t)(h-t+27)*64; float a=0.f;
        #pragma unroll
        for (int d=0;d<64;d++) a = fmaf(qs[d], r[d], a);
        bh[((size_t)g*S_+s)*28 + t] = a;
    } else if (t >= 32 && t < 60){
        const int l = t-32;
        const float* r = rw + (size_t)(w-l+27)*64; float a=0.f;
        #pragma unroll
        for (int d=0;d<64;d++) a = fmaf(qs[d], r[d], a);
        bw[((size_t)g*S_+s)*28 + l] = a;
    }
}

// all 7 weight transposes in one kernel
__global__ void wsplit_all(
    const float* s0, const float* s1, const float* s2, const float* s3,
    const float* s4, const float* s5, const float* s6,
    fp16* d0, fp16* d1, fp16* d2, fp16* d3, fp16* d4, fp16* d5, fp16* d6)
{
    int t = blockIdx.x;
    const float* src; fp16* dst; int K, N, loc;
    if      (t <  3072){ src=s0; dst=d0; K=C_;     N=3*C_;  loc=t; }
    else if (t <  4096){ src=s1; dst=d1; K=C_;     N=C_;    loc=t-3072; }
    else if (t <  8192){ src=s2; dst=d2; K=C_;     N=HID_;  loc=t-4096; }
    else if (t < 12288){ src=s3; dst=d3; K=HID_;   N=C_;    loc=t-8192; }
    else if (t < 12800){ src=s4; dst=d4; K=C_;     N=BC_;   loc=t-12288; }
    else if (t < 15104){ src=s5; dst=d5; K=9*BC_;  N=BC_;   loc=t-12800; }
    else               { src=s6; dst=d6; K=BC_;    N=C_;    loc=t-15104; }
    int kt = K >> 5;
    int k0 = (loc % kt) * 32, n0 = (loc / kt) * 32;

    __shared__ float s[32][33];
    const int tx = threadIdx.x, ty = threadIdx.y;
    #pragma unroll
    for (int y=0;y<32;y+=8) s[ty+y][tx] = src[(size_t)(k0+ty+y)*N + n0+tx];
    __syncthreads();
    #pragma unroll
    for (int y=0;y<32;y+=8)
        dst[(size_t)(n0+ty+y)*K + k0+tx] = __float2half_rn(s[tx][ty+y]);
}

constexpr int SM128 = (2*128*40 + 128*40)*2*2;   // 61440 B
#define GSA(p, sym) cudaGetSymbolAddress((void**)&p, sym)
extern "C" void kernel_launch(void* const* d_in, const int* in_sizes, int n_in,
                              void* d_out, int out_size)
{
    const float *x=(const float*)d_in[0], *n1w=(const float*)d_in[1], *n1b=(const float*)d_in[2],
        *qkvw=(const float*)d_in[3], *qkvb=(const float*)d_in[4], *pw=(const float*)d_in[5],
        *pb=(const float*)d_in[6], *relh=(const float*)d_in[7], *relw=(const float*)d_in[8],
        *n2w=(const float*)d_in[9], *n2b=(const float*)d_in[10], *f1w=(const float*)d_in[11],
        *f1b=(const float*)d_in[12], *f2w=(const float*)d_in[13], *f2b=(const float*)d_in[14],
        *c1w=(const float*)d_in[15], *l1w=(const float*)d_in[16], *l1b=(const float*)d_in[17],
        *c2w=(const float*)d_in[18], *l2w=(const float*)d_in[19], *l2b=(const float*)d_in[20],
        *c3w=(const float*)d_in[21], *l3w=(const float*)d_in[22], *l3b=(const float*)d_in[23];
    float* out = (float*)d_out;

    float *qkv,*bh,*bw,*attn,*x1,*x2,*c1,*c2,*c3;
    float2 *pstat;
    fp16 *xnh,*xnl,*qh,*ql,*kh,*vTh,*aoh,*aol,*mh,*ml,*x2h,*x2l,*c1h,*c1l,*c2h,*c2l;
    fp16 *wah,*wbh,*wch,*wdh,*weh,*wfh,*wgh;
    GSA(qkv,g_qkv); GSA(bh,g_bh); GSA(bw,g_bw); GSA(attn,g_attn); GSA(x1,g_x1); GSA(x2,g_x2);
    GSA(c1,g_c1); GSA(c2,g_c2); GSA(c3,g_c3); GSA(pstat,g_pstat);
    GSA(xnh,g_xnh); GSA(xnl,g_xnl); GSA(qh,g_qh); GSA(ql,g_ql); GSA(kh,g_kh);
    GSA(vTh,g_vTh); GSA(aoh,g_aoh); GSA(aol,g_aol);
    GSA(mh,g_mh); GSA(ml,g_ml); GSA(x2h,g_x2h); GSA(x2l,g_x2l);
    GSA(c1h,g_c1h); GSA(c1l,g_c1l); GSA(c2h,g_c2h); GSA(c2l,g_c2l);
    GSA(wah,g_wah); GSA(wbh,g_wbh); GSA(wch,g_wch); GSA(wdh,g_wdh);
    GSA(weh,g_weh); GSA(wfh,g_wfh); GSA(wgh,g_wgh);

    cudaFuncSetAttribute(mma_gemm<128,0,0>, cudaFuncAttributeMaxDynamicSharedMemorySize, SM128);
    cudaFuncSetAttribute(mma_gemm<128,1,0>, cudaFuncAttributeMaxDynamicSharedMemorySize, SM128);
    cudaFuncSetAttribute(mma_gemm<128,2,0>, cudaFuncAttributeMaxDynamicSharedMemorySize, SM128);
    cudaFuncSetAttribute(mma_gemm<128,3,0>, cudaFuncAttributeMaxDynamicSharedMemorySize, SM128);
    cudaFuncSetAttribute(mma_gemm<128,5,0>, cudaFuncAttributeMaxDynamicSharedMemorySize, SM128);
    cudaFuncSetAttribute(mma_gemm<128,0,1>, cudaFuncAttributeMaxDynamicSharedMemorySize, SM128);

    wsplit_all<<<15616, dim3(32,8)>>>(qkvw, pw, f1w, f2w, c1w, c2w, c3w,
                                      wah, wbh, wch, wdh, weh, wfh, wgh);

    ln_k<<<M_,256>>>(x, n1w, n1b, nullptr, xnh, xnl, C_, 1e-5f, 0, nullptr);
    mma_gemm<128,0,0><<<dim3(49,24,1),256,SM128>>>(xnh,xnl,wah, qkv,nullptr,nullptr,
        M_,3*C_,C_, C_,C_,3*C_, 0,0,0, qkvb,nullptr,0,nullptr,nullptr,nullptr);
    repack_k<<<dim3(25,G_),256>>>(qkv,qh,ql,kh,vTh);
    relbias_k<<<G_*S_,64>>>(qkv,relh,relw,bh,bw);
    mma_gemm<128,3,0><<<dim3(7,7,G_),256,SM128>>>(qh,ql,kh, attn,nullptr,nullptr,
        S_,S_,64, 64,64,S_, (long long)S_*64,(long long)S_*64,(long long)S_*S_,
        nullptr,nullptr,0,bh,bw,pstat);
    av_k<<<dim3(7,G_),256>>>(attn, pstat, vTh, aoh, aol);
    mma_gemm<128,2,0><<<dim3(49,8,1),256,SM128>>>(aoh,aol,wbh, x1,nullptr,nullptr,
        M_,C_,C_, C_,C_,C_, 0,0,0, pb,x,C_,nullptr,nullptr,nullptr);
    ln_k<<<M_,256>>>(x1, n2w, n2b, nullptr, xnh, xnl, C_, 1e-5f, 0, nullptr);
    mma_gemm<128,1,0><<<dim3(49,32,1),256,SM128>>>(xnh,xnl,wch, nullptr,mh,ml,
        M_,HID_,C_, C_,C_,HID_, 0,0,0, f1b,nullptr,0,nullptr,nullptr,nullptr);
    mma_gemm<128,5,0><<<dim3(49,8,1),256,SM128>>>(mh,ml,wdh, x2,x2h,x2l,
        M_,C_,HID_, HID_,HID_,C_, 0,0,0, f2b,x1,C_,nullptr,nullptr,nullptr);
    mma_gemm<128,0,0><<<dim3(49,4,1),256,SM128>>>(x2h,x2l,weh, c1,nullptr,nullptr,
        M_,BC_,C_, C_,C_,BC_, 0,0,0, nullptr,nullptr,0,nullptr,nullptr,nullptr);
    ln_k<<<M_,256>>>(c1, l1w, l1b, nullptr, c1h, c1l, BC_, 1e-6f, 1, nullptr);
    mma_gemm<128,0,1><<<dim3(49,4,1),256,SM128>>>(c1h,c1l,wfh, c2,nullptr,nullptr,
        M_,BC_,9*BC_, 0,9*BC_,BC_, 0,0,0, nullptr,nullptr,0,nullptr,nullptr,nullptr);
    ln_k<<<M_,256>>>(c2, l2w, l2b, nullptr, c2h, c2l, BC_, 1e-6f, 1, nullptr);
    mma_gemm<128,0,0><<<dim3(49,8,1),256,SM128>>>(c2h,c2l,wgh, c3,nullptr,nullptr,
        M_,C_,BC_, BC_,BC_,C_, 0,0,0, nullptr,nullptr,0,nullptr,nullptr,nullptr);
    ln_k<<<M_,256>>>(c3, l3w, l3b, out, nullptr, nullptr, C_, 1e-6f, 2, x2);
}

// round 12
// speedup vs baseline: 1.1572x; 1.0576x over previous
#include <cuda_runtime.h>
#include <cuda_fp16.h>
#include <mma.h>
#include <math.h>
#include <stdint.h>

using namespace nvcuda;
typedef __half fp16;
constexpr int C_=1024, S_=784, M_=6272, HID_=4096, BC_=512, G_=128;

__device__ __align__(16) fp16 g_xnh[M_*C_], g_xnl[M_*C_];
__device__ __align__(16) float g_qkv[M_*3*C_];
__device__ __align__(16) fp16 g_qh[G_*S_*64], g_ql[G_*S_*64], g_kh[G_*S_*64];
__device__ __align__(16) fp16 g_vTh[G_*64*S_];
__device__ __align__(16) float g_bh[G_*S_*28], g_bw[G_*S_*28];
__device__ __align__(16) float g_attn[(size_t)G_*S_*S_];
__device__ __align__(16) fp16 g_aoh[M_*C_], g_aol[M_*C_];
__device__ __align__(16) float g_x1[M_*C_];
__device__ __align__(16) fp16 g_mh[M_*HID_], g_ml[M_*HID_];
__device__ __align__(16) float g_x2[M_*C_];
__device__ __align__(16) fp16 g_x2h[M_*C_], g_x2l[M_*C_];
__device__ __align__(16) float g_c1[M_*BC_];
__device__ __align__(16) fp16 g_c1h[M_*BC_], g_c1l[M_*BC_];
__device__ __align__(16) float g_c2[M_*BC_];
__device__ __align__(16) fp16 g_c2h[M_*BC_], g_c2l[M_*BC_];
__device__ __align__(16) float g_c3[M_*C_];
__device__ __align__(16) fp16 g_wah[3*C_*C_];
__device__ __align__(16) fp16 g_wbh[C_*C_];
__device__ __align__(16) fp16 g_wch[HID_*C_];
__device__ __align__(16) fp16 g_wdh[C_*HID_];
__device__ __align__(16) fp16 g_weh[BC_*C_];
__device__ __align__(16) fp16 g_wfh[BC_*9*BC_];
__device__ __align__(16) fp16 g_wgh[C_*BC_];

__device__ __forceinline__ float gelu_f(float x){ return 0.5f*x*(1.0f+erff(x*0.7071067811865475f)); }
__device__ __forceinline__ void split2(float x, fp16&h, fp16&l){
    h = __float2half_rn(x); l = __float2half_rn(x - __half2float(h));
}

__device__ __forceinline__ void cp16(fp16* sm, const fp16* gm, bool pred){
    uint32_t sa = (uint32_t)__cvta_generic_to_shared(sm);
    int sz = pred ? 16 : 0;
    asm volatile("cp.async.ca.shared.global [%0], [%1], 16, %2;" :: "r"(sa), "l"(gm), "r"(sz));
}
#define CP_COMMIT() asm volatile("cp.async.commit_group;")

__device__ __forceinline__ void stage_tile(const fp16* __restrict__ src, int ld,
        int row0, int rmax, int k0, int K, fp16* sm, int tid, int rows){
    for (int i = tid; i < rows*4; i += 256){
        int r = i>>2, cq = i&3;
        int gr = row0 + r, gk = k0 + (cq<<3);
        bool p = (gr < rmax && gk < K);
        cp16(sm + r*40 + (cq<<3), p ? src + (size_t)gr*ld + gk : src, p);
    }
}
__device__ __forceinline__ void stage_conv(const fp16* __restrict__ src, int row0, int k0,
        fp16* sm, int tid){
    int ky = k0/1536, kxr = k0 - ky*1536, kx = kxr>>9, ci0 = kxr&511;
    for (int i = tid; i < 512; i += 256){
        int r = i>>2, cq = i&3;
        int gr = row0 + r;
        bool p = false; const fp16* g = src;
        if (gr < M_){
            int b = gr/S_, rem = gr - b*S_, h = rem/28, w = rem - h*28;
            int ih = h+ky-1, iw = w+kx-1;
            if ((unsigned)ih<28u && (unsigned)iw<28u){
                p = true; g = src + ((size_t)((b*28+ih)*28+iw))*BC_ + ci0 + (cq<<3);
            }
        }
        cp16(sm + r*40 + (cq<<3), g, p);
    }
}

// fp16x2 wmma GEMM: D = (Ah+Al)@Bh^T, 2-stage cp.async pipeline. B given as [N,K].
// EPI 0: fp32(+bias)  1: gelu->split  2: +bias+res->fp32  3: +bh+bw->fp32
// EPI 5: +bias+res->fp32 AND split
template<int BN, int EPI, int GATHER>
__global__ void __launch_bounds__(256) mma_gemm(
    const fp16* __restrict__ Ah, const fp16* __restrict__ Al,
    const fp16* __restrict__ Bh,
    float* __restrict__ o0, fp16* __restrict__ o1, fp16* __restrict__ o2,
    int M, int N, int K, int lda, int ldb, int ldc,
    long long sA, long long sB, long long sC,
    const float* __restrict__ bias, const float* __restrict__ res, int ldres,
    const float* __restrict__ bhp, const float* __restrict__ bwp)
{
    constexpr int BM = 128;
    constexpr int WarpsN = 4, WarpsM = 2;
    constexpr int WM = BM/WarpsM, WN = BN/WarpsN;
    constexpr int MI = WM/16, NI = WN/16;
    constexpr int ATILE = BM*40, BTILE = BN*40;
    constexpr int STAGE = 2*ATILE + BTILE;
    extern __shared__ __align__(128) fp16 pool[];

    const int tid = threadIdx.x, warp = tid>>5, lane = tid&31;
    const int bm = blockIdx.x*BM, bn = blockIdx.y*BN, g = blockIdx.z;
    Ah += (size_t)g*sA; Al += (size_t)g*sA; Bh += (size_t)g*sB;
    const int wrow = (warp/WarpsN)*WM, wcol = (warp%WarpsN)*WN;

    wmma::fragment<wmma::accumulator,16,16,16,float> acc[MI][NI];
    #pragma unroll
    for (int mi=0; mi<MI; mi++)
        #pragma unroll
        for (int ni=0; ni<NI; ni++) wmma::fill_fragment(acc[mi][ni], 0.f);

    const int KC = (K+31)>>5;
    auto issue = [&](int kc, int s){
        fp16* st = pool + s*STAGE;
        int k0 = kc<<5;
        if (GATHER){ stage_conv(Ah, bm, k0, st, tid); stage_conv(Al, bm, k0, st+ATILE, tid); }
        else { stage_tile(Ah, lda, bm, M, k0, K, st, tid, BM);
               stage_tile(Al, lda, bm, M, k0, K, st+ATILE, tid, BM); }
        stage_tile(Bh, ldb, bn, N, k0, K, st+2*ATILE, tid, BN);
        CP_COMMIT();
    };
    issue(0, 0);
    for (int kc = 0; kc < KC; kc++){
        int buf = kc & 1;
        if (kc+1 < KC){
            issue(kc+1, buf^1);
            asm volatile("cp.async.wait_group 1;");
        } else {
            asm volatile("cp.async.wait_group 0;");
        }
        __syncthreads();
        fp16 *Ash = pool + buf*STAGE, *Asl = Ash + ATILE, *Bsh = Ash + 2*ATILE;
        #pragma unroll
        for (int ks=0; ks<2; ks++){
            wmma::fragment<wmma::matrix_b,16,16,16,fp16,wmma::col_major> bh_f[NI];
            #pragma unroll
            for (int ni=0; ni<NI; ni++)
                wmma::load_matrix_sync(bh_f[ni], Bsh + (wcol+ni*16)*40 + ks*16, 40);
            #pragma unroll
            for (int mi=0; mi<MI; mi++){
                wmma::fragment<wmma::matrix_a,16,16,16,fp16,wmma::row_major> ah_f, al_f;
                wmma::load_matrix_sync(ah_f, Ash + (wrow+mi*16)*40 + ks*16, 40);
                wmma::load_matrix_sync(al_f, Asl + (wrow+mi*16)*40 + ks*16, 40);
                #pragma unroll
                for (int ni=0; ni<NI; ni++){
                    wmma::mma_sync(acc[mi][ni], ah_f, bh_f[ni], acc[mi][ni]);
                    wmma::mma_sync(acc[mi][ni], al_f, bh_f[ni], acc[mi][ni]);
                }
            }
        }
        __syncthreads();
    }

    float* eb = reinterpret_cast<float*>(pool) + warp*320;   // 16x20
    #pragma unroll
    for (int mi=0; mi<MI; mi++){
        #pragma unroll
        for (int ni=0; ni<NI; ni++){
            wmma::store_matrix_sync(eb, acc[mi][ni], 20, wmma::mem_row_major);
            __syncwarp();
            int row0 = bm + wrow + mi*16, col0 = bn + wcol + ni*16;
            #pragma unroll
            for (int j=0; j<8; j++){
                int e = lane + j*32, r = e>>4, c = e&15;
                int gr = row0 + r, gc = col0 + c;
                if (gr < M && gc < N){
                    float v = eb[r*20 + c];
                    if (bias) v += bias[gc];
                    if (EPI == 1){ v = gelu_f(v); fp16 h,l; split2(v,h,l);
                        o1[(size_t)gr*ldc+gc]=h; o2[(size_t)gr*ldc+gc]=l; }
                    else if (EPI == 2){ o0[(size_t)gr*ldc+gc] = v + res[(size_t)gr*ldres+gc]; }
                    else if (EPI == 3){
                        v += bhp[((size_t)g*S_+gr)*28 + gc/28] + bwp[((size_t)g*S_+gr)*28 + gc%28];
                        o0[(size_t)g*sC + (size_t)gr*ldc + gc] = v; }
                    else if (EPI == 5){ v += res[(size_t)gr*ldres+gc];
                        o0[(size_t)gr*ldc+gc] = v; fp16 h,l; split2(v,h,l);
                        o1[(size_t)gr*ldc+gc]=h; o2[(size_t)gr*ldc+gc]=l; }
                    else o0[(size_t)gr*ldc+gc] = v;
                }
            }
            __syncwarp();
        }
    }
}

// fused stats + softmax + AV: O[g] = softmax(attn[g]) @ V[g]^T, scatter split
__global__ void __launch_bounds__(256) av_k(
    const float* __restrict__ attn,
    const fp16* __restrict__ vT, fp16* __restrict__ oh, fp16* __restrict__ ol)
{
    constexpr int KC = 25;
    __shared__ __align__(16) fp16 Ph[2][128*40], Pl[2][128*40], Vs[2][64*40];
    __shared__ float2 st[128];
    const int tid = threadIdx.x, warp = tid>>5, lane = tid&31;
    const int bm = blockIdx.x*128, g = blockIdx.y;
    attn += (size_t)g*S_*S_;
    vT   += (size_t)g*64*S_;
    const int wrow = (warp>>1)*32, wcol = (warp&1)*32;

    // kick off first V stage while computing stats
    stage_tile(vT, S_, 0, 64, 0, S_, Vs[0], tid, 64);
    CP_COMMIT();

    // phase 0: per-row softmax stats (warp per 16 rows, registers only)
    for (int rr = 0; rr < 16; rr++){
        int r = warp*16 + rr;
        int grow = bm + r;
        float vbuf[25];
        float m = -1e30f;
        if (grow < S_){
            const float* p = attn + (size_t)grow*S_;
            #pragma unroll
            for (int i=0;i<25;i++){
                int col = lane + i*32;
                vbuf[i] = (col < S_) ? p[col] : -1e30f;
                m = fmaxf(m, vbuf[i]);
            }
        } else {
            #pragma unroll
            for (int i=0;i<25;i++) vbuf[i] = -1e30f;
        }
        #pragma unroll
        for (int o=16;o;o>>=1) m = fmaxf(m, __shfl_xor_sync(~0u, m, o));
        float s = 0.f;
        if (grow < S_){
            #pragma unroll
            for (int i=0;i<25;i++){
                int col = lane + i*32;
                if (col < S_) s += __expf(vbuf[i] - m);
            }
        }
        #pragma unroll
        for (int o=16;o;o>>=1) s += __shfl_xor_sync(~0u, s, o);
        if (lane == 0)
            st[r] = (grow < S_) ? make_float2(m, 1.f/s) : make_float2(0.f, 0.f);
    }

    wmma::fragment<wmma::accumulator,16,16,16,float> acc[2][2];
    #pragma unroll
    for (int mi=0; mi<2; mi++)
        #pragma unroll
        for (int ni=0; ni<2; ni++) wmma::fill_fragment(acc[mi][ni], 0.f);

    float4 areg[4];
    auto loadA = [&](int kc){
        int k0 = kc<<5;
        #pragma unroll
        for (int j=0; j<4; j++){
            int s = tid + j*256, r = s>>3, cq = s&7;
            int row = bm + r, col = k0 + cq*4;
            if (row < S_ && col+3 < S_)
                areg[j] = *reinterpret_cast<const float4*>(attn + (size_t)row*S_ + col);
            else if (row < S_){
                float t0 = (col   < S_) ? attn[(size_t)row*S_ + col  ] : -1e30f;
                float t1 = (col+1 < S_) ? attn[(size_t)row*S_ + col+1] : -1e30f;
                float t2 = (col+2 < S_) ? attn[(size_t)row*S_ + col+2] : -1e30f;
                float t3 = (col+3 < S_) ? attn[(size_t)row*S_ + col+3] : -1e30f;
                areg[j] = make_float4(t0,t1,t2,t3);
            } else areg[j] = make_float4(-1e30f,-1e30f,-1e30f,-1e30f);
        }
    };
    loadA(0);
    __syncthreads();   // st[] ready

    for (int kc = 0; kc < KC; kc++){
        int buf = kc & 1;
        #pragma unroll
        for (int j=0; j<4; j++){
            int s = tid + j*256, r = s>>3, cq = s&7;
            float m = st[r].x, inv = st[r].y;
            bool rv = (bm + r) < S_;
            union { fp16 h[4]; uint2 u; } ph, pl;
            float* av = reinterpret_cast<float*>(&areg[j]);
            #pragma unroll
            for (int u=0; u<4; u++){
                float p = rv ? __expf(av[u] - m) * inv : 0.f;
                split2(p, ph.h[u], pl.h[u]);
            }
            *reinterpret_cast<uint2*>(&Ph[buf][r*40 + cq*4]) = ph.u;
            *reinterpret_cast<uint2*>(&Pl[buf][r*40 + cq*4]) = pl.u;
        }
        if (kc+1 < KC){
            loadA(kc+1);
            stage_tile(vT, S_, 0, 64, (kc+1)<<5, S_, Vs[buf^1], tid, 64);
            CP_COMMIT();
            asm volatile("cp.async.wait_group 1;");
        } else {
            asm volatile("cp.async.wait_group 0;");
        }
        __syncthreads();
        #pragma unroll
        for (int ks=0; ks<2; ks++){
            wmma::fragment<wmma::matrix_b,16,16,16,fp16,wmma::col_major> b_f[2];
            #pragma unroll
            for (int ni=0; ni<2; ni++)
                wmma::load_matrix_sync(b_f[ni], Vs[buf] + (wcol+ni*16)*40 + ks*16, 40);
            #pragma unroll
            for (int mi=0; mi<2; mi++){
                wmma::fragment<wmma::matrix_a,16,16,16,fp16,wmma::row_major> ah_f, al_f;
                wmma::load_matrix_sync(ah_f, Ph[buf] + (wrow+mi*16)*40 + ks*16, 40);
                wmma::load_matrix_sync(al_f, Pl[buf] + (wrow+mi*16)*40 + ks*16, 40);
                #pragma unroll
                for (int ni=0; ni<2; ni++){
                    wmma::mma_sync(acc[mi][ni], ah_f, b_f[ni], acc[mi][ni]);
                    wmma::mma_sync(acc[mi][ni], al_f, b_f[ni], acc[mi][ni]);
                }
            }
        }
        __syncthreads();
    }

    float* eb = reinterpret_cast<float*>(Ph) + warp*320;
    #pragma unroll
    for (int mi=0; mi<2; mi++){
        #pragma unroll
        for (int ni=0; ni<2; ni++){
            wmma::store_matrix_sync(eb, acc[mi][ni], 20, wmma::mem_row_major);
            __syncwarp();
            int row0 = bm + wrow + mi*16, col0 = wcol + ni*16;
            #pragma unroll
            for (int j=0; j<8; j++){
                int e = lane + j*32, r = e>>4, c = e&15;
                int gr = row0 + r, gc = col0 + c;
                if (gr < S_){
                    size_t o = ((size_t)(g>>4)*S_ + gr)*1024 + (size_t)(g&15)*64 + gc;
                    fp16 h,l; split2(eb[r*20 + c], h, l);
                    oh[o]=h; ol[o]=l;
                }
            }
            __syncwarp();
        }
    }
}

__global__ void ln_k(const float* __restrict__ x, const float* __restrict__ w,
                     const float* __restrict__ bp, float* __restrict__ of,
                     fp16* __restrict__ oh, fp16* __restrict__ ol,
                     int Cw, float eps, int mode, const float* __restrict__ res)
{
    __shared__ float r1[8], r2[8], st[2];
    const int row = blockIdx.x, tid = threadIdx.x, lane = tid&31, wd = tid>>5;
    const float* xr = x + (size_t)row*Cw;
    float s=0.f, sq=0.f;
    for (int i = tid; i < Cw; i += 256){ float t = xr[i]; s += t; sq += t*t; }
    #pragma unroll
    for (int o=16;o;o>>=1){ s+=__shfl_down_sync(~0u,s,o); sq+=__shfl_down_sync(~0u,sq,o); }
    if (lane==0){ r1[wd]=s; r2[wd]=sq; }
    __syncthreads();
    if (tid==0){ float S=0,Q=0; for(int i=0;i<8;i++){S+=r1[i];Q+=r2[i];}
        float m=S/Cw, v=Q/Cw-m*m; st[0]=m; st[1]=rsqrtf(v+eps); }
    __syncthreads();
    float mean=st[0], rstd=st[1];
    for (int i = tid; i < Cw; i += 256){
        float y = (xr[i]-mean)*rstd*w[i] + bp[i];
        if (mode==2) of[(size_t)row*Cw+i] = y + res[(size_t)row*Cw+i];
        else { if (mode==1) y = gelu_f(y);
            fp16 h,l; split2(y,h,l); oh[(size_t)row*Cw+i]=h; ol[(size_t)row*Cw+i]=l; }
    }
}

__global__ void repack_k(const float* __restrict__ qkv,
    fp16* __restrict__ qh, fp16* __restrict__ ql, fp16* __restrict__ kh,
    fp16* __restrict__ vTh)
{
    __shared__ float sv[32][65];
    const int g = blockIdx.y, s0 = blockIdx.x*32, b = g>>4, n = g&15, t = threadIdx.x;
    for (int e = t; e < 2048; e += 256){
        int sl = e>>6, d = e&63, s = s0+sl;
        if (s < S_){
            size_t base = ((size_t)(b*S_+s))*3072 + n*64 + d;
            float qv = qkv[base]*0.125f;
            sv[sl][d] = qkv[base+2048];
            size_t o = ((size_t)g*S_+s)*64 + d;
            fp16 h,l; split2(qv,h,l); qh[o]=h; ql[o]=l;
            kh[o] = __float2half_rn(qkv[base+1024]);
        }
    }
    __syncthreads();
    for (int e = t; e < 2048; e += 256){
        int d = e>>5, j = e&31, s = s0+j;
        if (s < S_)
            vTh[((size_t)g*64+d)*S_ + s] = __float2half_rn(sv[j][d]);
    }
}

__global__ void relbias_k(const float* __restrict__ qkv, const float* __restrict__ rh,
                          const float* __restrict__ rw, float* __restrict__ bh, float* __restrict__ bw)
{
    const int s = blockIdx.x % S_, g = blockIdx.x / S_, b = g>>4, n = g&15;
    __shared__ float qs[64];
    const int t = threadIdx.x;
    qs[t] = qkv[((size_t)(b*S_+s))*3072 + n*64 + t];
    __syncthreads();
    const int h = s/28, w = s%28;
    if (t < 28){
        const float* r = rh + (size_t)(h-t+27)*64; float a=0.f;
        #pragma unroll
        for (int d=0;d<64;d++) a = fmaf(qs[d], r[d], a);
        bh[((size_t)g*S_+s)*28 + t] = a;
    } else if (t >= 32 && t < 60){
        const int l = t-32;
        const float* r = rw + (size_t)(w-l+27)*64; float a=0.f;
        #pragma unroll
        for (int d=0;d<64;d++) a = fmaf(qs[d], r[d], a);
        bw[((size_t)g*S_+s)*28 + l] = a;
    }
}

// all 7 weight transposes in one kernel
__global__ void wsplit_all(
    const float* s0, const float* s1, const float* s2, const float* s3,
    const float* s4, const float* s5, const float* s6,
    fp16* d0, fp16* d1, fp16* d2, fp16* d3, fp16* d4, fp16* d5, fp16* d6)
{
    int t = blockIdx.x;
    const float* src; fp16* dst; int K, N, loc;
    if      (t <  3072){ src=s0; dst=d0; K=C_;     N=3*C_;  loc=t; }
    else if (t <  4096){ src=s1; dst=d1; K=C_;     N=C_;    loc=t-3072; }
    else if (t <  8192){ src=s2; dst=d2; K=C_;     N=HID_;  loc=t-4096; }
    else if (t < 12288){ src=s3; dst=d3; K=HID_;   N=C_;    loc=t-8192; }
    else if (t < 12800){ src=s4; dst=d4; K=C_;     N=BC_;   loc=t-12288; }
    else if (t < 15104){ src=s5; dst=d5; K=9*BC_;  N=BC_;   loc=t-12800; }
    else               { src=s6; dst=d6; K=BC_;    N=C_;    loc=t-15104; }
    int kt = K >> 5;
    int k0 = (loc % kt) * 32, n0 = (loc / kt) * 32;

    __shared__ float s[32][33];
    const int tx = threadIdx.x, ty = threadIdx.y;
    #pragma unroll
    for (int y=0;y<32;y+=8) s[ty+y][tx] = src[(size_t)(k0+ty+y)*N + n0+tx];
    __syncthreads();
    #pragma unroll
    for (int y=0;y<32;y+=8)
        dst[(size_t)(n0+ty+y)*K + k0+tx] = __float2half_rn(s[tx][ty+y]);
}

constexpr int SM128 = (2*128*40 + 128*40)*2*2;   // 61440 B
#define GSA(p, sym) cudaGetSymbolAddress((void**)&p, sym)
extern "C" void kernel_launch(void* const* d_in, const int* in_sizes, int n_in,
                              void* d_out, int out_size)
{
    const float *x=(const float*)d_in[0], *n1w=(const float*)d_in[1], *n1b=(const float*)d_in[2],
        *qkvw=(const float*)d_in[3], *qkvb=(const float*)d_in[4], *pw=(const float*)d_in[5],
        *pb=(const float*)d_in[6], *relh=(const float*)d_in[7], *relw=(const float*)d_in[8],
        *n2w=(const float*)d_in[9], *n2b=(const float*)d_in[10], *f1w=(const float*)d_in[11],
        *f1b=(const float*)d_in[12], *f2w=(const float*)d_in[13], *f2b=(const float*)d_in[14],
        *c1w=(const float*)d_in[15], *l1w=(const float*)d_in[16], *l1b=(const float*)d_in[17],
        *c2w=(const float*)d_in[18], *l2w=(const float*)d_in[19], *l2b=(const float*)d_in[20],
        *c3w=(const float*)d_in[21], *l3w=(const float*)d_in[22], *l3b=(const float*)d_in[23];
    float* out = (float*)d_out;

    float *qkv,*bh,*bw,*attn,*x1,*x2,*c1,*c2,*c3;
    fp16 *xnh,*xnl,*qh,*ql,*kh,*vTh,*aoh,*aol,*mh,*ml,*x2h,*x2l,*c1h,*c1l,*c2h,*c2l;
    fp16 *wah,*wbh,*wch,*wdh,*weh,*wfh,*wgh;
    GSA(qkv,g_qkv); GSA(bh,g_bh); GSA(bw,g_bw); GSA(attn,g_attn); GSA(x1,g_x1); GSA(x2,g_x2);
    GSA(c1,g_c1); GSA(c2,g_c2); GSA(c3,g_c3);
    GSA(xnh,g_xnh); GSA(xnl,g_xnl); GSA(qh,g_qh); GSA(ql,g_ql); GSA(kh,g_kh);
    GSA(vTh,g_vTh); GSA(aoh,g_aoh); GSA(aol,g_aol);
    GSA(mh,g_mh); GSA(ml,g_ml); GSA(x2h,g_x2h); GSA(x2l,g_x2l);
    GSA(c1h,g_c1h); GSA(c1l,g_c1l); GSA(c2h,g_c2h); GSA(c2l,g_c2l);
    GSA(wah,g_wah); GSA(wbh,g_wbh); GSA(wch,g_wch); GSA(wdh,g_wdh);
    GSA(weh,g_weh); GSA(wfh,g_wfh); GSA(wgh,g_wgh);

    cudaFuncSetAttribute(mma_gemm<128,0,0>, cudaFuncAttributeMaxDynamicSharedMemorySize, SM128);
    cudaFuncSetAttribute(mma_gemm<128,1,0>, cudaFuncAttributeMaxDynamicSharedMemorySize, SM128);
    cudaFuncSetAttribute(mma_gemm<128,2,0>, cudaFuncAttributeMaxDynamicSharedMemorySize, SM128);
    cudaFuncSetAttribute(mma_gemm<128,3,0>, cudaFuncAttributeMaxDynamicSharedMemorySize, SM128);
    cudaFuncSetAttribute(mma_gemm<128,5,0>, cudaFuncAttributeMaxDynamicSharedMemorySize, SM128);
    cudaFuncSetAttribute(mma_gemm<128,0,1>, cudaFuncAttributeMaxDynamicSharedMemorySize, SM128);

    wsplit_all<<<15616, dim3(32,8)>>>(qkvw, pw, f1w, f2w, c1w, c2w, c3w,
                                      wah, wbh, wch, wdh, weh, wfh, wgh);

    ln_k<<<M_,256>>>(x, n1w, n1b, nullptr, xnh, xnl, C_, 1e-5f, 0, nullptr);
    mma_gemm<128,0,0><<<dim3(49,24,1),256,SM128>>>(xnh,xnl,wah, qkv,nullptr,nullptr,
        M_,3*C_,C_, C_,C_,3*C_, 0,0,0, qkvb,nullptr,0,nullptr,nullptr);
    repack_k<<<dim3(25,G_),256>>>(qkv,qh,ql,kh,vTh);
    relbias_k<<<G_*S_,64>>>(qkv,relh,relw,bh,bw);
    mma_gemm<128,3,0><<<dim3(7,7,G_),256,SM128>>>(qh,ql,kh, attn,nullptr,nullptr,
        S_,S_,64, 64,64,S_, (long long)S_*64,(long long)S_*64,(long long)S_*S_,
        nullptr,nullptr,0,bh,bw);
    av_k<<<dim3(7,G_),256>>>(attn, vTh, aoh, aol);
    mma_gemm<128,2,0><<<dim3(49,8,1),256,SM128>>>(aoh,aol,wbh, x1,nullptr,nullptr,
        M_,C_,C_, C_,C_,C_, 0,0,0, pb,x,C_,nullptr,nullptr);
    ln_k<<<M_,256>>>(x1, n2w, n2b, nullptr, xnh, xnl, C_, 1e-5f, 0, nullptr);
    mma_gemm<128,1,0><<<dim3(49,32,1),256,SM128>>>(xnh,xnl,wch, nullptr,mh,ml,
        M_,HID_,C_, C_,C_,HID_, 0,0,0, f1b,nullptr,0,nullptr,nullptr);
    mma_gemm<128,5,0><<<dim3(49,8,1),256,SM128>>>(mh,ml,wdh, x2,x2h,x2l,
        M_,C_,HID_, HID_,HID_,C_, 0,0,0, f2b,x1,C_,nullptr,nullptr);
    mma_gemm<128,0,0><<<dim3(49,4,1),256,SM128>>>(x2h,x2l,weh, c1,nullptr,nullptr,
        M_,BC_,C_, C_,C_,BC_, 0,0,0, nullptr,nullptr,0,nullptr,nullptr);
    ln_k<<<M_,256>>>(c1, l1w, l1b, nullptr, c1h, c1l, BC_, 1e-6f, 1, nullptr);
    mma_gemm<128,0,1><<<dim3(49,4,1),256,SM128>>>(c1h,c1l,wfh, c2,nullptr,nullptr,
        M_,BC_,9*BC_, 0,9*BC_,BC_, 0,0,0, nullptr,nullptr,0,nullptr,nullptr);
    ln_k<<<M_,256>>>(c2, l2w, l2b, nullptr, c2h, c2l, BC_, 1e-6f, 1, nullptr);
    mma_gemm<128,0,0><<<dim3(49,8,1),256,SM128>>>(c2h,c2l,wgh, c3,nullptr,nullptr,
        M_,C_,BC_, BC_,BC_,C_, 0,0,0, nullptr,nullptr,0,nullptr,nullptr);
    ln_k<<<M_,256>>>(c3, l3w, l3b, out, nullptr, nullptr, C_, 1e-6f, 2, x2);
}